// round 2
// baseline (speedup 1.0000x reference)
#include <cuda_runtime.h>
#include <math.h>

#define NN 40000
#define EE 320000
#define DD 128
#define HH 4
#define TT 3
#define RR 5
#define KKM 3
#define DKK 32
#define ND (NN*DD)
#define INV_SQRT_DK 0.17677669529663687f   // 1/sqrt(32)

// ---------------- scratch (device globals; no allocation allowed) -------------
__device__ float    g_q[ND];
__device__ float    g_k[ND];
__device__ float    g_v[ND];
__device__ float    g_qA[NN*RR*DD];
__device__ float    g_logits[EE*HH];     // logits, then exp() in place
__device__ unsigned g_mx[NN*HH];         // encoded float max
__device__ float    g_sum[NN*HH];
__device__ int      g_deg[NN];
__device__ float    g_agg[KKM*ND];
__device__ float    g_aggm[KKM*ND];
__device__ float    g_qlin[ND];
__device__ float    g_front[KKM*ND];
__device__ float    g_tail[KKM*ND];
__device__ float    g_res[ND];
__device__ int      g_list[NN];
__device__ int      g_cnt[TT];
__device__ int      g_off[TT];
__device__ int      g_cur[TT];

// ---------------- helpers ----------------
__device__ __forceinline__ unsigned enc_f(float f) {
    unsigned u = __float_as_uint(f);
    return (u & 0x80000000u) ? ~u : (u | 0x80000000u);
}
__device__ __forceinline__ float dec_f(unsigned u) {
    return (u & 0x80000000u) ? __uint_as_float(u & 0x7fffffffu) : __uint_as_float(~u);
}
__device__ __forceinline__ float signed_cbrt(float a) {
    float s = (a > 0.f) ? 1.f : ((a < 0.f) ? -1.f : 0.f);
    return s * cbrtf(fabsf(a) + 1e-18f);
}
__device__ __forceinline__ float gelu_exact(float x) {
    return 0.5f * x * (1.f + erff(x * 0.70710678118654752440f));
}
__device__ __forceinline__ float warp_sum(float p) {
    #pragma unroll
    for (int o = 16; o > 0; o >>= 1) p += __shfl_xor_sync(0xffffffffu, p, o);
    return p;
}

// ---------------- init / bucketing ----------------
__global__ void k_init() {
    int i = blockIdx.x * blockDim.x + threadIdx.x;
    int stride = gridDim.x * blockDim.x;
    for (int j = i; j < NN * HH; j += stride) { g_mx[j] = 0u; g_sum[j] = 0.f; }
    for (int j = i; j < NN; j += stride) g_deg[j] = 0;
    if (i < TT) { g_cnt[i] = 0; g_cur[i] = 0; }
}
__global__ void k_count(const int* __restrict__ nt) {
    int n = blockIdx.x * blockDim.x + threadIdx.x;
    if (n < NN) atomicAdd(&g_cnt[nt[n]], 1);
}
__global__ void k_offs() {
    int o = 0;
    for (int t = 0; t < TT; t++) { g_off[t] = o; g_cur[t] = o; o += g_cnt[t]; }
}
__global__ void k_scatter(const int* __restrict__ nt) {
    int n = blockIdx.x * blockDim.x + threadIdx.x;
    if (n < NN) {
        int p = atomicAdd(&g_cur[nt[n]], 1);
        g_list[p] = n;
    }
}

// ---------------- generic 128-wide GEMM -------------------
// C[row,:] = X[row,:] @ W + B   for 128x128 W. BM=64, BK=8, 256 threads.
// typed==1: blockIdx.y = node type t; rows from g_list segment; W += t*D*D.
// typed==0: blockIdx.y = batch index; pointers advanced by *_stride_y.
__global__ void gemm128_kernel(
    const float* __restrict__ X, long long xs,
    const float* __restrict__ W, long long ws,
    const float* __restrict__ B, long long bs,
    float* __restrict__ C, long long cs,
    int typed, int nrows, int root_gy)
{
    int gy = blockIdx.y;
    const int* rows = nullptr;
    int cnt;
    if (typed) {
        rows = g_list + g_off[gy];
        cnt = g_cnt[gy];
        W += (long long)gy * DD * DD;
        if (B) B += (long long)gy * DD;
    } else {
        X += (long long)gy * xs;
        W += (long long)gy * ws;
        if (B) B += (long long)gy * bs;
        C += (long long)gy * cs;
        cnt = nrows;
    }
    int bm = blockIdx.x * 64;
    if (bm >= cnt) return;
    bool doroot = (root_gy == gy);

    __shared__ float Xs[64][8];
    __shared__ float Ws[8][128];
    int tid = threadIdx.x, ty = tid >> 5, tx = tid & 31;

    float acc[8][4];
    #pragma unroll
    for (int i = 0; i < 8; i++)
        #pragma unroll
        for (int j = 0; j < 4; j++) acc[i][j] = 0.f;

    for (int kb = 0; kb < 16; kb++) {
        // load X tile (gathered rows) 64x8
        {
            int m = tid >> 2;
            int kq = (tid & 3) << 1;
            float2 xv = make_float2(0.f, 0.f);
            int gr = bm + m;
            if (gr < cnt) {
                int row = rows ? rows[gr] : gr;
                xv = *(const float2*)(X + (long long)row * DD + kb * 8 + kq);
            }
            if (doroot) { xv.x = signed_cbrt(xv.x); xv.y = signed_cbrt(xv.y); }
            Xs[m][kq] = xv.x; Xs[m][kq + 1] = xv.y;
            int kk = tid >> 5;
            int c4 = (tid & 31) << 2;
            *(float4*)&Ws[kk][c4] = *(const float4*)(W + (long long)(kb * 8 + kk) * DD + c4);
        }
        __syncthreads();
        #pragma unroll
        for (int kk = 0; kk < 8; kk++) {
            float4 b = *(float4*)&Ws[kk][tx << 2];
            #pragma unroll
            for (int i = 0; i < 8; i++) {
                float a = Xs[ty * 8 + i][kk];
                acc[i][0] += a * b.x; acc[i][1] += a * b.y;
                acc[i][2] += a * b.z; acc[i][3] += a * b.w;
            }
        }
        __syncthreads();
    }
    float4 bb = make_float4(0.f, 0.f, 0.f, 0.f);
    if (B) bb = *(const float4*)(B + (tx << 2));
    #pragma unroll
    for (int i = 0; i < 8; i++) {
        int gr = bm + ty * 8 + i;
        if (gr < cnt) {
            int row = rows ? rows[gr] : gr;
            float4 o;
            o.x = acc[i][0] + bb.x; o.y = acc[i][1] + bb.y;
            o.z = acc[i][2] + bb.z; o.w = acc[i][3] + bb.w;
            *(float4*)(C + (long long)row * DD + (tx << 2)) = o;
        }
    }
}

// ---------------- qA = rel_att-transformed q, per node per relation ----------
// qA[n,r,h,d] = sum_m rel_att[r,h,d,m] * q[n,h,m]
__global__ void k_qA(const float* __restrict__ rel_att) {
    extern __shared__ float As[];   // permuted: As[(rh*32+m)*32+d] = A[rh,d,m]
    for (int i = threadIdx.x; i < RR * HH * DKK * DKK; i += blockDim.x) {
        int rh = i >> 10, dm = i & 1023, d = dm >> 5, m = dm & 31;
        As[(rh * 32 + m) * 32 + d] = rel_att[i];
    }
    __syncthreads();
    int lane = threadIdx.x & 31;
    int gw = (blockIdx.x * blockDim.x + threadIdx.x) >> 5;
    int nw = (gridDim.x * blockDim.x) >> 5;
    for (int n = gw; n < NN; n += nw) {
        float qr[HH];
        #pragma unroll
        for (int h = 0; h < HH; h++) qr[h] = g_q[n * DD + h * 32 + lane];
        #pragma unroll
        for (int h = 0; h < HH; h++) {
            float a0 = 0, a1 = 0, a2 = 0, a3 = 0, a4 = 0;
            #pragma unroll
            for (int m = 0; m < 32; m++) {
                float qm = __shfl_sync(0xffffffffu, qr[h], m);
                int base = (h * 32 + m) * 32 + lane;    // r stride = 4096
                a0 += As[base        ] * qm;
                a1 += As[base +  4096] * qm;
                a2 += As[base +  8192] * qm;
                a3 += As[base + 12288] * qm;
                a4 += As[base + 16384] * qm;
            }
            g_qA[((n * RR + 0) * HH + h) * 32 + lane] = a0;
            g_qA[((n * RR + 1) * HH + h) * 32 + lane] = a1;
            g_qA[((n * RR + 2) * HH + h) * 32 + lane] = a2;
            g_qA[((n * RR + 3) * HH + h) * 32 + lane] = a3;
            g_qA[((n * RR + 4) * HH + h) * 32 + lane] = a4;
        }
    }
}

// ---------------- edge logits + segment max + degree ----------------
__global__ void k_logits(const int* __restrict__ ei, const int* __restrict__ et,
                         const float* __restrict__ rel_pri) {
    int lane = threadIdx.x & 31;
    int gw = (blockIdx.x * blockDim.x + threadIdx.x) >> 5;
    int nw = (gridDim.x * blockDim.x) >> 5;
    for (int e = gw; e < EE; e += nw) {
        int s = ei[e], tg = ei[EE + e], r = et[e];
        float p0, p1, p2, p3;
        {
            const float* kb = g_k + (long long)s * DD;
            const float* qa = g_qA + ((long long)tg * RR + r) * DD;
            p0 = kb[lane]       * qa[lane];
            p1 = kb[32 + lane]  * qa[32 + lane];
            p2 = kb[64 + lane]  * qa[64 + lane];
            p3 = kb[96 + lane]  * qa[96 + lane];
        }
        p0 = warp_sum(p0); p1 = warp_sum(p1); p2 = warp_sum(p2); p3 = warp_sum(p3);
        if (lane == 0) {
            atomicAdd(&g_deg[tg], 1);
            float l0 = p0 * rel_pri[r * HH + 0] * INV_SQRT_DK;
            float l1 = p1 * rel_pri[r * HH + 1] * INV_SQRT_DK;
            float l2 = p2 * rel_pri[r * HH + 2] * INV_SQRT_DK;
            float l3 = p3 * rel_pri[r * HH + 3] * INV_SQRT_DK;
            g_logits[e * HH + 0] = l0; g_logits[e * HH + 1] = l1;
            g_logits[e * HH + 2] = l2; g_logits[e * HH + 3] = l3;
            atomicMax(&g_mx[tg * HH + 0], enc_f(l0));
            atomicMax(&g_mx[tg * HH + 1], enc_f(l1));
            atomicMax(&g_mx[tg * HH + 2], enc_f(l2));
            atomicMax(&g_mx[tg * HH + 3], enc_f(l3));
        }
    }
}

// ---------------- exp + segment sum ----------------
__global__ void k_exp(const int* __restrict__ ei) {
    int idx = blockIdx.x * blockDim.x + threadIdx.x;
    if (idx >= EE * HH) return;
    int e = idx >> 2, h = idx & 3;
    int tg = ei[EE + e];
    float ex = expf(g_logits[idx] - dec_f(g_mx[tg * HH + h]));
    g_logits[idx] = ex;
    atomicAdd(&g_sum[tg * HH + h], ex);
}

// ---------------- messages / agg for edge-index n < N ----------------
// agg[k][n] = deg[n] * att[n,h] * vp^(k+1) ;  vp = v[src[n]] @ rel_msg[r]
__global__ void k_msg(const float* __restrict__ rel_msg, const int* __restrict__ ei,
                      const int* __restrict__ et) {
    extern __shared__ float Ms[];   // straight copy: Ms[((r*4+h)*32+d)*32+m]
    for (int i = threadIdx.x; i < RR * HH * DKK * DKK; i += blockDim.x) Ms[i] = rel_msg[i];
    __syncthreads();
    int lane = threadIdx.x & 31;
    int gw = (blockIdx.x * blockDim.x + threadIdx.x) >> 5;
    int nw = (gridDim.x * blockDim.x) >> 5;
    for (int n = gw; n < NN; n += nw) {
        int s = ei[n], tg = ei[EE + n], r = et[n];
        float deg = (float)g_deg[n];
        float vr[HH];
        #pragma unroll
        for (int h = 0; h < HH; h++) vr[h] = g_v[(long long)s * DD + h * 32 + lane];
        #pragma unroll
        for (int h = 0; h < HH; h++) {
            float att = g_logits[n * HH + h] / (g_sum[tg * HH + h] + 1e-16f);
            float vp = 0.f;
            const float* Mb = Ms + (r * HH + h) * 1024;
            #pragma unroll
            for (int d = 0; d < 32; d++) {
                float vd = __shfl_sync(0xffffffffu, vr[h], d);
                vp += Mb[d * 32 + lane] * vd;
            }
            float base = deg * att;
            int o = n * DD + h * 32 + lane;
            float vp2 = vp * vp;
            g_agg[o]          = base * vp;
            g_agg[ND + o]     = base * vp2;
            g_agg[2 * ND + o] = base * vp2 * vp;
        }
    }
}

// ---------------- gating: res = sum_k sigmoid(front_k . tail_k) * aggm_k -----
__global__ void k_gate() {
    int w = (blockIdx.x * blockDim.x + threadIdx.x) >> 5;
    int lane = threadIdx.x & 31;
    if (w >= NN) return;
    int o = w * DD + lane * 4;
    float4 r4 = make_float4(0.f, 0.f, 0.f, 0.f);
    #pragma unroll
    for (int k = 0; k < KKM; k++) {
        float4 f = *(float4*)&g_front[k * ND + o];
        float4 t = *(float4*)&g_tail[k * ND + o];
        float p = f.x * t.x + f.y * t.y + f.z * t.z + f.w * t.w;
        p = warp_sum(p);
        float gate = 1.f / (1.f + expf(-p));
        float4 a = *(float4*)&g_aggm[k * ND + o];
        r4.x += gate * a.x; r4.y += gate * a.y; r4.z += gate * a.z; r4.w += gate * a.w;
    }
    *(float4*)&g_res[o] = r4;
}

// ---------------- final typed GEMM: gelu -> a_w -> skip blend -> LayerNorm ---
__global__ void k_final(const float* __restrict__ aw, const float* __restrict__ ab,
                        const float* __restrict__ xin, const float* __restrict__ skip,
                        const float* __restrict__ lng, const float* __restrict__ lnb,
                        float* __restrict__ out) {
    int t = blockIdx.y;
    int cnt = g_cnt[t];
    int bm = blockIdx.x * 64;
    if (bm >= cnt) return;
    const int* rows = g_list + g_off[t];
    const float* W = aw + (long long)t * DD * DD;

    __shared__ float Xs[64][8];
    __shared__ float Ws[8][128];
    int tid = threadIdx.x, ty = tid >> 5, tx = tid & 31;

    float acc[8][4];
    #pragma unroll
    for (int i = 0; i < 8; i++)
        #pragma unroll
        for (int j = 0; j < 4; j++) acc[i][j] = 0.f;

    for (int kb = 0; kb < 16; kb++) {
        {
            int m = tid >> 2;
            int kq = (tid & 3) << 1;
            float2 xv = make_float2(0.f, 0.f);
            int gr = bm + m;
            if (gr < cnt) {
                int row = rows[gr];
                xv = *(const float2*)(g_res + (long long)row * DD + kb * 8 + kq);
                xv.x = gelu_exact(xv.x); xv.y = gelu_exact(xv.y);
            }
            Xs[m][kq] = xv.x; Xs[m][kq + 1] = xv.y;
            int kk = tid >> 5;
            int c4 = (tid & 31) << 2;
            *(float4*)&Ws[kk][c4] = *(const float4*)(W + (long long)(kb * 8 + kk) * DD + c4);
        }
        __syncthreads();
        #pragma unroll
        for (int kk = 0; kk < 8; kk++) {
            float4 b = *(float4*)&Ws[kk][tx << 2];
            #pragma unroll
            for (int i = 0; i < 8; i++) {
                float a = Xs[ty * 8 + i][kk];
                acc[i][0] += a * b.x; acc[i][1] += a * b.y;
                acc[i][2] += a * b.z; acc[i][3] += a * b.w;
            }
        }
        __syncthreads();
    }

    float alpha = 1.f / (1.f + expf(-skip[t]));
    float4 bias = *(const float4*)(ab  + t * DD + (tx << 2));
    float4 gg   = *(const float4*)(lng + t * DD + (tx << 2));
    float4 bb   = *(const float4*)(lnb + t * DD + (tx << 2));

    #pragma unroll
    for (int i = 0; i < 8; i++) {
        int gr = bm + ty * 8 + i;
        if (gr >= cnt) continue;
        int row = rows[gr];
        float4 xv = *(const float4*)(xin + (long long)row * DD + (tx << 2));
        float y0 = (acc[i][0] + bias.x) * alpha + xv.x * (1.f - alpha);
        float y1 = (acc[i][1] + bias.y) * alpha + xv.y * (1.f - alpha);
        float y2 = (acc[i][2] + bias.z) * alpha + xv.z * (1.f - alpha);
        float y3 = (acc[i][3] + bias.w) * alpha + xv.w * (1.f - alpha);
        float s  = y0 + y1 + y2 + y3;
        float ss = y0 * y0 + y1 * y1 + y2 * y2 + y3 * y3;
        #pragma unroll
        for (int o = 16; o > 0; o >>= 1) {
            s  += __shfl_xor_sync(0xffffffffu, s,  o);
            ss += __shfl_xor_sync(0xffffffffu, ss, o);
        }
        float mu  = s * (1.f / 128.f);
        float inv = rsqrtf(ss * (1.f / 128.f) - mu * mu + 1e-5f);
        float4 o4;
        o4.x = (y0 - mu) * inv * gg.x + bb.x;
        o4.y = (y1 - mu) * inv * gg.y + bb.y;
        o4.z = (y2 - mu) * inv * gg.z + bb.z;
        o4.w = (y3 - mu) * inv * gg.w + bb.w;
        *(float4*)(out + (long long)row * DD + (tx << 2)) = o4;
    }
}

// ---------------- launch ----------------
extern "C" void kernel_launch(void* const* d_in, const int* in_sizes, int n_in,
                              void* d_out, int out_size) {
    const float* meta_xs  = (const float*)d_in[0];
    const int*   node_type= (const int*)  d_in[1];
    const int*   edge_idx = (const int*)  d_in[2];
    const int*   edge_type= (const int*)  d_in[3];
    const float* q_w = (const float*)d_in[5],  *q_b = (const float*)d_in[6];
    const float* k_w = (const float*)d_in[7],  *k_b = (const float*)d_in[8];
    const float* v_w = (const float*)d_in[9],  *v_b = (const float*)d_in[10];
    const float* a_w = (const float*)d_in[11], *a_b = (const float*)d_in[12];
    const float* rel_pri = (const float*)d_in[13];
    const float* rel_att = (const float*)d_in[14];
    const float* rel_msg = (const float*)d_in[15];
    const float* WMk = (const float*)d_in[16];
    const float* Wak = (const float*)d_in[17];
    const float* Wq  = (const float*)d_in[18], *bq  = (const float*)d_in[19];
    const float* Wkl = (const float*)d_in[20], *bkl = (const float*)d_in[21];
    const float* skip= (const float*)d_in[22];
    const float* lng = (const float*)d_in[23], *lnb = (const float*)d_in[24];
    float* out = (float*)d_out;

    cudaFuncSetAttribute(k_qA,  cudaFuncAttributeMaxDynamicSharedMemorySize, 81920);
    cudaFuncSetAttribute(k_msg, cudaFuncAttributeMaxDynamicSharedMemorySize, 81920);

    void *pq, *pk, *pv, *pagg, *paggm, *pqlin, *pfront, *ptail;
    cudaGetSymbolAddress(&pq, g_q);
    cudaGetSymbolAddress(&pk, g_k);
    cudaGetSymbolAddress(&pv, g_v);
    cudaGetSymbolAddress(&pagg, g_agg);
    cudaGetSymbolAddress(&paggm, g_aggm);
    cudaGetSymbolAddress(&pqlin, g_qlin);
    cudaGetSymbolAddress(&pfront, g_front);
    cudaGetSymbolAddress(&ptail, g_tail);

    k_init<<<512, 256>>>();
    k_count<<<(NN + 255) / 256, 256>>>(node_type);
    k_offs<<<1, 1>>>();
    k_scatter<<<(NN + 255) / 256, 256>>>(node_type);

    dim3 gT((NN + 63) / 64, TT);
    dim3 gP3((NN + 63) / 64, KKM);
    dim3 gP1((NN + 63) / 64, 1);

    // typed projections q,k,v
    gemm128_kernel<<<gT, 256>>>(meta_xs, 0, q_w, 0, q_b, 0, (float*)pq, 0, 1, 0, -1);
    gemm128_kernel<<<gT, 256>>>(meta_xs, 0, k_w, 0, k_b, 0, (float*)pk, 0, 1, 0, -1);
    gemm128_kernel<<<gT, 256>>>(meta_xs, 0, v_w, 0, v_b, 0, (float*)pv, 0, 1, 0, -1);

    // qA precompute, edge logits, softmax
    k_qA<<<592, 256, 81920>>>(rel_att);
    k_logits<<<2368, 256>>>(edge_idx, edge_type, rel_pri);
    k_exp<<<(EE * HH + 255) / 256, 256>>>(edge_idx);

    // messages / agg (edge-index < N shortcut)
    k_msg<<<592, 256, 81920>>>(rel_msg, edge_idx, edge_type);

    // aggm[k] = root_if_last(agg[k]) @ WMk[k]
    gemm128_kernel<<<gP3, 256>>>((const float*)pagg, ND, WMk, DD * DD, nullptr, 0,
                                 (float*)paggm, ND, 0, NN, KKM - 1);
    // qlin = x @ Wq + bq
    gemm128_kernel<<<gP1, 256>>>(meta_xs, 0, Wq, 0, bq, 0, (float*)pqlin, 0, 0, NN, -1);
    // front[k] = qlin @ Wak[k]
    gemm128_kernel<<<gP3, 256>>>((const float*)pqlin, 0, Wak, DD * DD, nullptr, 0,
                                 (float*)pfront, ND, 0, NN, -1);
    // tail[k] = aggm[k] @ Wkl + bkl
    gemm128_kernel<<<gP3, 256>>>((const float*)paggm, ND, Wkl, 0, bkl, 0,
                                 (float*)ptail, ND, 0, NN, -1);

    // gating -> res
    k_gate<<<(NN * 32 + 255) / 256, 256>>>();

    // gelu -> typed a_w -> skip blend -> LayerNorm -> out
    k_final<<<gT, 256>>>(a_w, a_b, meta_xs, skip, lng, lnb, out);
}